// round 8
// baseline (speedup 1.0000x reference)
#include <cuda_runtime.h>
#include <cstdint>

// ---------------------------------------------------------------------------
// SpGraphAttentionLayer (GAT forward).  N=50000, D=128, O=128, R=64, E=1e6.
//
// Factored form:
//   u = a2 @ a  (320) ; c = u[256:320]
//   sdot_s[n] = x[n]·u[0:128] ; sdot_d[n] = x[n]·u[128:256]
//   score[e]  = sdot_s[src] + sdot_d[dst] + emb[e]·c
//   ee[e]     = exp(-leaky(score))
//   rs[n] = Σ ee ; w[n] = Σ ee·emb[e] (R^64) ; y[n] = Σ ee·x[dst] (R^128)
//   out[n] = rs>0 ? elu( [x[n], y[n]/rs, w[n]/rs] @ a^T ) : 0
//
// Aggregation is gather-based over a per-launch CSR (no FP atomics):
//   hist -> scan -> scatter (eid,dst packed) -> node kernel (warp per node).
// ---------------------------------------------------------------------------

#define NMAX 50000
#define EMAX 1100000
#define GAT_ALPHA 0.2f

__device__ float g_sdot[(size_t)NMAX * 2];
__device__ float g_u[320];
__device__ float g_rowsum[NMAX];
__device__ float g_w[(size_t)NMAX * 64];
__device__ float g_y[(size_t)NMAX * 128];
__device__ float g_aT[320 * 128];          // a transposed: [k][o]
__device__ int       g_cnt[NMAX];
__device__ int       g_off[NMAX + 1];
__device__ int       g_cur[NMAX];
__device__ long long g_adj[EMAX];          // (eid<<32) | dst

__device__ __forceinline__ void fma2(unsigned long long &acc,
                                     unsigned long long a, unsigned long long b) {
    asm("fma.rn.f32x2 %0, %1, %2, %0;" : "+l"(acc) : "l"(a), "l"(b));
}
__device__ __forceinline__ float2 unpack2(unsigned long long v) {
    float2 r;
    asm("mov.b64 {%0, %1}, %2;" : "=f"(r.x), "=f"(r.y) : "l"(v));
    return r;
}

// ---------------------------------------------------------------------------
__global__ void vec_kernel(const float* __restrict__ a, const float* __restrict__ a2) {
    __shared__ float a2s[128];
    int t = threadIdx.x;
    if (t < 128) a2s[t] = a2[t];
    __syncthreads();
    if (t < 320) {
        float acc = 0.f;
        #pragma unroll 8
        for (int o = 0; o < 128; o++) acc += a2s[o] * a[o * 320 + t];
        g_u[t] = acc;
    }
}

// ---------------------------------------------------------------------------
__global__ void transpose_a_kernel(const float* __restrict__ a) {
    int idx = blockIdx.x * 256 + threadIdx.x;
    if (idx < 320 * 128) {
        int k = idx >> 7, o = idx & 127;
        g_aT[idx] = a[o * 320 + k];
    }
}

// ---------------------------------------------------------------------------
__global__ void __launch_bounds__(128) sdot_kernel(const float* __restrict__ x, int N) {
    __shared__ float us[256];
    int t = threadIdx.x;
    us[t] = g_u[t];
    us[t + 128] = g_u[t + 128];
    __syncthreads();

    int n = blockIdx.x * 4 + (t >> 5);
    if (n >= N) return;
    int lane = t & 31;
    float ps = 0.f, pd = 0.f;
    #pragma unroll
    for (int j = 0; j < 4; j++) {
        float xv = x[(size_t)n * 128 + lane + 32 * j];
        ps += xv * us[lane + 32 * j];
        pd += xv * us[128 + lane + 32 * j];
    }
    #pragma unroll
    for (int off = 16; off; off >>= 1) {
        ps += __shfl_xor_sync(0xffffffffu, ps, off);
        pd += __shfl_xor_sync(0xffffffffu, pd, off);
    }
    if (lane == 0) { g_sdot[2 * n] = ps; g_sdot[2 * n + 1] = pd; }
}

// ---------------------------------------------------------------------------
// CSR build
// ---------------------------------------------------------------------------
__global__ void cnt_zero_kernel(int N) {
    int i = blockIdx.x * blockDim.x + threadIdx.x;
    if (i < N) g_cnt[i] = 0;
}

__global__ void hist_kernel(const int* __restrict__ e1, const int* __restrict__ e2,
                            int E1, int E2) {
    int E = E1 + E2;
    int stride = gridDim.x * blockDim.x;
    for (int e = blockIdx.x * blockDim.x + threadIdx.x; e < E; e += stride) {
        int s = (e < E1) ? e1[e] : e2[e - E1];
        atomicAdd(&g_cnt[s], 1);
    }
}

// single block, 1024 threads: exclusive scan of g_cnt[0..N) -> g_off, g_cur
__global__ void __launch_bounds__(1024) scan_kernel(int N) {
    __shared__ int sums[1024];
    int t = threadIdx.x;
    int CH = (N + 1023) >> 10;
    int lo = t * CH;
    int hi = lo + CH; if (hi > N) hi = N; if (lo > N) lo = N;

    int s = 0;
    for (int i = lo; i < hi; i++) s += g_cnt[i];
    sums[t] = s;
    __syncthreads();

    // Hillis-Steele inclusive scan
    for (int off = 1; off < 1024; off <<= 1) {
        int v = (t >= off) ? sums[t - off] : 0;
        __syncthreads();
        sums[t] += v;
        __syncthreads();
    }

    int run = (t > 0) ? sums[t - 1] : 0;
    for (int i = lo; i < hi; i++) {
        int c = g_cnt[i];
        g_off[i] = run;
        g_cur[i] = run;
        run += c;
    }
    if (t == 1023) g_off[N] = run;
}

__global__ void scatter_kernel(const int* __restrict__ e1, const int* __restrict__ e2,
                               int E1, int E2) {
    int E = E1 + E2;
    int stride = gridDim.x * blockDim.x;
    for (int e = blockIdx.x * blockDim.x + threadIdx.x; e < E; e += stride) {
        int s, d;
        if (e < E1) { s = e1[e]; d = e1[E1 + e]; }
        else { int g2 = e - E1; s = e2[g2]; d = e2[E2 + g2]; }
        int pos = atomicAdd(&g_cur[s], 1);
        g_adj[pos] = ((long long)e << 32) | (unsigned int)d;
    }
}

// ---------------------------------------------------------------------------
// Node kernel: one warp per node, gather over CSR, register accumulators,
// one STG set per node. No FP atomics anywhere.
// Half-warp h handles edges i+h per 2-edge phase; sub = lane&15.
// wa: w[sub*4..+3]; y0/y1: y[sub*8..+7]. Merge halves at the end (xor 16).
// ---------------------------------------------------------------------------
__global__ void __launch_bounds__(256) node_kernel(
    const float* __restrict__ x, const float* __restrict__ emb1,
    const float* __restrict__ emb2, int E1, int N)
{
    const int warp = threadIdx.x >> 5;
    const int lane = threadIdx.x & 31;
    const int sub  = lane & 15;
    const int half = lane >> 4;
    const int n = blockIdx.x * 8 + warp;
    if (n >= N) return;

    const int off0 = g_off[n];
    const int deg  = g_off[n + 1] - off0;

    const float4 c4 = *(const float4*)(g_u + 256 + sub * 4);
    const float ssn = g_sdot[2 * n];

    float4 wa = make_float4(0.f, 0.f, 0.f, 0.f);
    float4 y0 = make_float4(0.f, 0.f, 0.f, 0.f);
    float4 y1 = make_float4(0.f, 0.f, 0.f, 0.f);
    float rs = 0.f;

    for (int i = 0; i < deg; i += 2) {
        int j = i + half;
        bool valid = (j < deg);
        long long pk = g_adj[off0 + (valid ? j : 0)];
        int d   = (int)(pk & 0xffffffffLL);
        int eid = (int)(pk >> 32);
        const float* ep = (eid < E1) ? (emb1 + (size_t)eid * 64)
                                     : (emb2 + (size_t)(eid - E1) * 64);
        float4 em = __ldg((const float4*)ep + sub);

        float p = em.x * c4.x + em.y * c4.y + em.z * c4.z + em.w * c4.w;
        p += __shfl_xor_sync(0xffffffffu, p, 1);
        p += __shfl_xor_sync(0xffffffffu, p, 2);
        p += __shfl_xor_sync(0xffffffffu, p, 4);
        p += __shfl_xor_sync(0xffffffffu, p, 8);

        float sc = p + ssn + g_sdot[2 * d + 1];
        float pw = sc > 0.f ? sc : GAT_ALPHA * sc;
        float ee = valid ? __expf(-pw) : 0.f;

        if (sub == 0) rs += ee;
        wa.x += ee * em.x; wa.y += ee * em.y;
        wa.z += ee * em.z; wa.w += ee * em.w;

        const float4* xp = (const float4*)(x + (size_t)d * 128);
        float4 xv0 = __ldg(xp + sub * 2);
        float4 xv1 = __ldg(xp + sub * 2 + 1);
        y0.x += ee * xv0.x; y0.y += ee * xv0.y;
        y0.z += ee * xv0.z; y0.w += ee * xv0.w;
        y1.x += ee * xv1.x; y1.y += ee * xv1.y;
        y1.z += ee * xv1.z; y1.w += ee * xv1.w;
    }

    // merge the two halves
    #define MRG(v) v += __shfl_xor_sync(0xffffffffu, v, 16)
    MRG(wa.x); MRG(wa.y); MRG(wa.z); MRG(wa.w);
    MRG(y0.x); MRG(y0.y); MRG(y0.z); MRG(y0.w);
    MRG(y1.x); MRG(y1.y); MRG(y1.z); MRG(y1.w);
    MRG(rs);
    #undef MRG

    if (half == 0) {
        *(float4*)(g_w + (size_t)n * 64 + sub * 4) = wa;
        *(float4*)(g_y + (size_t)n * 128 + sub * 8) = y0;
        *(float4*)(g_y + (size_t)n * 128 + sub * 8 + 4) = y1;
        if (sub == 0) g_rowsum[n] = rs;
    }
}

// ---------------------------------------------------------------------------
// Final GEMM: out[64n x 128o] = elu( z @ a^T ), z = [x | y/rs | w/rs] (K=320).
// ---------------------------------------------------------------------------
__global__ void __launch_bounds__(256) final_kernel(
    const float* __restrict__ x, float* __restrict__ out, int N)
{
    __shared__ float2 z_sm[64 * 65];
    __shared__ float  a_sm[64 * 132];
    __shared__ float  inv_sm[64];

    const int tid = threadIdx.x;
    const int warp = tid >> 5, lane = tid & 31;
    const int n0 = blockIdx.x * 64;

    const int ob = (warp & 1) * 64;
    const int nb = (warp >> 1) * 16;
    const int nloc = nb + (lane >> 3) * 4;
    const int o0 = ob + (lane & 7) * 8;

    if (tid < 64) {
        float rs = (n0 + tid < N) ? g_rowsum[n0 + tid] : 0.f;
        inv_sm[tid] = rs > 0.f ? 1.f / rs : 0.f;
    }

    unsigned long long acc[4][4];
    #pragma unroll
    for (int j = 0; j < 4; j++)
        #pragma unroll
        for (int p = 0; p < 4; p++) acc[j][p] = 0ull;

    #pragma unroll
    for (int kc = 0; kc < 5; kc++) {
        __syncthreads();
        #pragma unroll
        for (int it = 0; it < 8; it++) {
            int i = tid + it * 256;
            int k = i >> 5, qq = i & 31;
            float4 av = *(const float4*)(g_aT + (size_t)(kc * 64 + k) * 128 + qq * 4);
            *(float4*)&a_sm[k * 132 + qq * 4] = av;
        }
        #pragma unroll
        for (int it = 0; it < 16; it++) {
            int i = tid + it * 256;
            int n = i >> 6, k = i & 63;
            float val = 0.f;
            if (n0 + n < N) {
                if (kc < 2)       val = x[(size_t)(n0 + n) * 128 + kc * 64 + k];
                else if (kc < 4)  val = g_y[(size_t)(n0 + n) * 128 + (kc - 2) * 64 + k] * inv_sm[n];
                else              val = g_w[(size_t)(n0 + n) * 64 + k] * inv_sm[n];
            }
            z_sm[n * 65 + k] = make_float2(val, val);
        }
        __syncthreads();

        #pragma unroll 8
        for (int k = 0; k < 64; k++) {
            ulonglong2 A01 = *(const ulonglong2*)&a_sm[k * 132 + o0];
            ulonglong2 A23 = *(const ulonglong2*)&a_sm[k * 132 + o0 + 4];
            #pragma unroll
            for (int j = 0; j < 4; j++) {
                unsigned long long zd = *(const unsigned long long*)&z_sm[(nloc + j) * 65 + k];
                fma2(acc[j][0], zd, A01.x);
                fma2(acc[j][1], zd, A01.y);
                fma2(acc[j][2], zd, A23.x);
                fma2(acc[j][3], zd, A23.y);
            }
        }
    }

    #pragma unroll
    for (int j = 0; j < 4; j++) {
        int n = n0 + nloc + j;
        if (n < N) {
            bool ok = inv_sm[nloc + j] > 0.f;
            float o[8];
            #pragma unroll
            for (int p = 0; p < 4; p++) {
                float2 f = unpack2(acc[j][p]);
                o[2 * p] = f.x; o[2 * p + 1] = f.y;
            }
            #pragma unroll
            for (int q = 0; q < 8; q++)
                o[q] = ok ? (o[q] > 0.f ? o[q] : expm1f(o[q])) : 0.f;
            float* dp = out + (size_t)n * 128 + o0;
            *(float4*)dp = make_float4(o[0], o[1], o[2], o[3]);
            *(float4*)(dp + 4) = make_float4(o[4], o[5], o[6], o[7]);
        }
    }
}

// ---------------------------------------------------------------------------
extern "C" void kernel_launch(void* const* d_in, const int* in_sizes, int n_in,
                              void* d_out, int out_size) {
    const float* x     = (const float*)d_in[0];
    const int*   edge1 = (const int*)  d_in[1];
    const float* emb1  = (const float*)d_in[2];
    const int*   edge2 = (const int*)  d_in[3];
    const float* emb2  = (const float*)d_in[4];
    const float* a     = (const float*)d_in[5];
    const float* a2    = (const float*)d_in[6];
    float* out = (float*)d_out;

    int N  = in_sizes[0] / 128;
    int E1 = in_sizes[1] / 2;
    int E2 = in_sizes[3] / 2;

    vec_kernel<<<1, 320>>>(a, a2);
    transpose_a_kernel<<<160, 256>>>(a);
    sdot_kernel<<<(N + 3) / 4, 128>>>(x, N);
    cnt_zero_kernel<<<(N + 1023) / 1024, 1024>>>(N);
    hist_kernel<<<1024, 256>>>(edge1, edge2, E1, E2);
    scan_kernel<<<1, 1024>>>(N);
    scatter_kernel<<<1024, 256>>>(edge1, edge2, E1, E2);
    node_kernel<<<(N + 7) / 8, 256>>>(x, emb1, emb2, E1, N);
    final_kernel<<<(N + 63) / 64, 256>>>(x, out, N);
}

// round 9
// speedup vs baseline: 1.0185x; 1.0185x over previous
#include <cuda_runtime.h>
#include <cstdint>

// ---------------------------------------------------------------------------
// SpGraphAttentionLayer (GAT forward).  N=50000, D=128, O=128, R=64, E=1e6.
//
// Factored form:
//   u = a2 @ a  (320) ; c = u[256:320]
//   sdot_s[n] = x[n]·u[0:128] ; sdot_d[n] = x[n]·u[128:256]
//   score[e]  = sdot_s[src] + sdot_d[dst] + emb[e]·c
//   ee[e]     = exp(-leaky(score))
//   rs[n] = Σ ee ; w[n] = Σ ee·emb[e] (R^64) ; y[n] = Σ ee·x[dst] (R^128)
//   out[n] = rs>0 ? elu( [x[n], y[n]/rs, w[n]/rs] @ a^T ) : 0
//
// Hybrid aggregation:
//   Pass A (streaming): ee + scatter w (red.v4) + store (ee,dst) to CSR slot.
//   Node kernel (gather): y,rs from (ee,dst) list, batched x-gather MLP=8.
// ---------------------------------------------------------------------------

#define NMAX 50000
#define EMAX 1100000
#define GAT_ALPHA 0.2f

__device__ float g_sdot[(size_t)NMAX * 2];
__device__ float g_u[320];
__device__ float g_rowsum[NMAX];
__device__ float g_w[(size_t)NMAX * 64];
__device__ float g_y[(size_t)NMAX * 128];
__device__ float g_aT[320 * 128];
__device__ int       g_cnt[NMAX];
__device__ int       g_off[NMAX + 1];
__device__ int       g_cur[NMAX];
__device__ long long g_adj[EMAX];          // (bits(ee)<<32) | dst

__device__ __forceinline__ void fma2(unsigned long long &acc,
                                     unsigned long long a, unsigned long long b) {
    asm("fma.rn.f32x2 %0, %1, %2, %0;" : "+l"(acc) : "l"(a), "l"(b));
}
__device__ __forceinline__ float2 unpack2(unsigned long long v) {
    float2 r;
    asm("mov.b64 {%0, %1}, %2;" : "=f"(r.x), "=f"(r.y) : "l"(v));
    return r;
}

// ---------------------------------------------------------------------------
__global__ void vec_kernel(const float* __restrict__ a, const float* __restrict__ a2) {
    __shared__ float a2s[128];
    int t = threadIdx.x;
    if (t < 128) a2s[t] = a2[t];
    __syncthreads();
    if (t < 320) {
        float acc = 0.f;
        #pragma unroll 8
        for (int o = 0; o < 128; o++) acc += a2s[o] * a[o * 320 + t];
        g_u[t] = acc;
    }
}

// ---------------------------------------------------------------------------
__global__ void transpose_a_kernel(const float* __restrict__ a) {
    int idx = blockIdx.x * 256 + threadIdx.x;
    if (idx < 320 * 128) {
        int k = idx >> 7, o = idx & 127;
        g_aT[idx] = a[o * 320 + k];
    }
}

// ---------------------------------------------------------------------------
__global__ void __launch_bounds__(128) sdot_kernel(const float* __restrict__ x, int N) {
    __shared__ float us[256];
    int t = threadIdx.x;
    us[t] = g_u[t];
    us[t + 128] = g_u[t + 128];
    __syncthreads();

    int n = blockIdx.x * 4 + (t >> 5);
    if (n >= N) return;
    int lane = t & 31;
    float ps = 0.f, pd = 0.f;
    #pragma unroll
    for (int j = 0; j < 4; j++) {
        float xv = x[(size_t)n * 128 + lane + 32 * j];
        ps += xv * us[lane + 32 * j];
        pd += xv * us[128 + lane + 32 * j];
    }
    #pragma unroll
    for (int off = 16; off; off >>= 1) {
        ps += __shfl_xor_sync(0xffffffffu, ps, off);
        pd += __shfl_xor_sync(0xffffffffu, pd, off);
    }
    if (lane == 0) { g_sdot[2 * n] = ps; g_sdot[2 * n + 1] = pd; }
}

// ---------------------------------------------------------------------------
// zero g_w + g_cnt
// ---------------------------------------------------------------------------
__global__ void zero_kernel(int N) {
    int stride = gridDim.x * blockDim.x;
    int i = blockIdx.x * blockDim.x + threadIdx.x;
    int nw = N * 16;
    float4 z = make_float4(0.f, 0.f, 0.f, 0.f);
    for (int j = i; j < nw; j += stride) ((float4*)g_w)[j] = z;
    for (int j = i; j < N; j += stride) g_cnt[j] = 0;
}

__global__ void hist_kernel(const int* __restrict__ e1, const int* __restrict__ e2,
                            int E1, int E2) {
    int E = E1 + E2;
    int stride = gridDim.x * blockDim.x;
    for (int e = blockIdx.x * blockDim.x + threadIdx.x; e < E; e += stride) {
        int s = (e < E1) ? e1[e] : e2[e - E1];
        atomicAdd(&g_cnt[s], 1);
    }
}

// single block, 1024 threads: exclusive scan of g_cnt -> g_off, g_cur
__global__ void __launch_bounds__(1024) scan_kernel(int N) {
    __shared__ int sums[1024];
    int t = threadIdx.x;
    int CH = (N + 1023) >> 10;
    int lo = t * CH;
    int hi = lo + CH; if (hi > N) hi = N; if (lo > N) lo = N;

    int s = 0;
    for (int i = lo; i < hi; i++) s += g_cnt[i];
    sums[t] = s;
    __syncthreads();

    for (int off = 1; off < 1024; off <<= 1) {
        int v = (t >= off) ? sums[t - off] : 0;
        __syncthreads();
        sums[t] += v;
        __syncthreads();
    }

    int run = (t > 0) ? sums[t - 1] : 0;
    for (int i = lo; i < hi; i++) {
        int c = g_cnt[i];
        g_off[i] = run;
        g_cur[i] = run;
        run += c;
    }
    if (t == 1023) g_off[N] = run;
}

// ---------------------------------------------------------------------------
// Pass A: streaming over edges (registers only, no smem/syncs).
// Warp owns 16 edges/chunk; half-warp h handles edges 2i+h in phase i.
//   - ee computed as round 7 (score dot via half-warp shuffles)
//   - scatter w[src] += ee*emb (red.v4, emb register-resident)
//   - store (ee,dst) packed 8B into CSR slot (atomicAdd g_cur[src])
// ---------------------------------------------------------------------------
__global__ void __launch_bounds__(256) passA_kernel(
    const int* __restrict__ edge1, const float* __restrict__ emb1,
    const int* __restrict__ edge2, const float* __restrict__ emb2,
    int E1i, int E2i)
{
    const long long E1 = E1i, E2 = E2i;
    const long long E = E1 + E2;
    const long long CH = (E + 15) >> 4;

    const int lane = threadIdx.x & 31;
    const int sub  = lane & 15;
    const int half = lane >> 4;

    long long gwarp = (long long)blockIdx.x * (blockDim.x >> 5) + (threadIdx.x >> 5);
    const long long nwarps = (long long)gridDim.x * (blockDim.x >> 5);

    const float4 c4 = *(const float4*)(g_u + 256 + sub * 4);

    for (long long ch = gwarp; ch < CH; ch += nwarps) {
        const long long base = ch << 4;

        long long ge = base + sub;
        long long gec = (ge < E) ? ge : (E - 1);
        int s, d;
        if (gec < E1) { s = edge1[gec]; d = edge1[E1 + gec]; }
        else { long long g2 = gec - E1; s = edge2[g2]; d = edge2[E2 + g2]; }
        float ssd = g_sdot[2 * s] + g_sdot[2 * d + 1];

        float4 em[8];
        float sc_mine = 0.f;
        #pragma unroll
        for (int i = 0; i < 8; i++) {
            long long e = base + 2 * i + half;
            if (e >= E) e = E - 1;
            const float* ep = (e < E1) ? (emb1 + e * 64) : (emb2 + (e - E1) * 64);
            em[i] = __ldg((const float4*)ep + sub);
            float p = em[i].x * c4.x + em[i].y * c4.y + em[i].z * c4.z + em[i].w * c4.w;
            p += __shfl_xor_sync(0xffffffffu, p, 1);
            p += __shfl_xor_sync(0xffffffffu, p, 2);
            p += __shfl_xor_sync(0xffffffffu, p, 4);
            p += __shfl_xor_sync(0xffffffffu, p, 8);
            float s0 = __shfl_sync(0xffffffffu, p, 0);
            float s1 = __shfl_sync(0xffffffffu, p, 16);
            if (lane == 2 * i)     sc_mine = s0;
            if (lane == 2 * i + 1) sc_mine = s1;
        }

        // softmax weight + CSR slot store on lanes 0..15
        float ee = 0.f;
        if (lane < 16 && ge < E) {
            float sc = sc_mine + ssd;
            float pw = sc > 0.f ? sc : GAT_ALPHA * sc;
            ee = __expf(-pw);
            int pos = atomicAdd(&g_cur[s], 1);
            g_adj[pos] = ((long long)(unsigned int)__float_as_uint(ee) << 32)
                       | (unsigned int)d;
        }

        // scatter w: phase i covers edges 2i (half 0) and 2i+1 (half 1)
        #pragma unroll
        for (int i = 0; i < 8; i++) {
            int j = 2 * i + half;
            float eej = __shfl_sync(0xffffffffu, ee, j);
            int   sij = __shfl_sync(0xffffffffu, s, j);
            float w0 = eej * em[i].x, w1 = eej * em[i].y;
            float w2 = eej * em[i].z, w3 = eej * em[i].w;
            float* wp = g_w + (size_t)sij * 64 + sub * 4;
            asm volatile("red.global.add.v4.f32 [%0], {%1, %2, %3, %4};"
                         :: "l"(wp), "f"(w0), "f"(w1), "f"(w2), "f"(w3) : "memory");
        }
    }
}

// ---------------------------------------------------------------------------
// Node kernel: warp per node. Gather (ee,dst), batch 8 x[dst] loads (MLP=8),
// accumulate y (float4/lane) + rs in registers, single STG per node.
// Invalid batch slots carry ee=0 (pk=0) and load x[0] (L1-hot) harmlessly.
// ---------------------------------------------------------------------------
__global__ void __launch_bounds__(256) node_kernel(const float* __restrict__ x, int N) {
    const int warp = threadIdx.x >> 5;
    const int lane = threadIdx.x & 31;
    const int n = blockIdx.x * 8 + warp;
    if (n >= N) return;

    const int off0 = g_off[n];
    const int deg  = g_off[n + 1] - off0;

    float4 acc = make_float4(0.f, 0.f, 0.f, 0.f);
    float rs = 0.f;

    for (int b = 0; b < deg; b += 8) {
        long long pk = 0;
        if (lane < 8 && b + lane < deg) pk = g_adj[off0 + b + lane];

        float eev[8];
        float4 xv[8];
        #pragma unroll
        for (int i = 0; i < 8; i++) {
            long long p = __shfl_sync(0xffffffffu, pk, i);
            int dd = (int)(p & 0xffffffffLL);
            eev[i] = __uint_as_float((unsigned int)((unsigned long long)p >> 32));
            xv[i] = __ldg((const float4*)(x + (size_t)dd * 128) + lane);
        }
        #pragma unroll
        for (int i = 0; i < 8; i++) {
            acc.x += eev[i] * xv[i].x;
            acc.y += eev[i] * xv[i].y;
            acc.z += eev[i] * xv[i].z;
            acc.w += eev[i] * xv[i].w;
            rs += eev[i];
        }
    }

    *(float4*)(g_y + (size_t)n * 128 + lane * 4) = acc;
    if (lane == 0) g_rowsum[n] = rs;
}

// ---------------------------------------------------------------------------
// Final GEMM: out[64n x 128o] = elu( z @ a^T ), z = [x | y/rs | w/rs] (K=320).
// ---------------------------------------------------------------------------
__global__ void __launch_bounds__(256) final_kernel(
    const float* __restrict__ x, float* __restrict__ out, int N)
{
    __shared__ float2 z_sm[64 * 65];
    __shared__ float  a_sm[64 * 132];
    __shared__ float  inv_sm[64];

    const int tid = threadIdx.x;
    const int warp = tid >> 5, lane = tid & 31;
    const int n0 = blockIdx.x * 64;

    const int ob = (warp & 1) * 64;
    const int nb = (warp >> 1) * 16;
    const int nloc = nb + (lane >> 3) * 4;
    const int o0 = ob + (lane & 7) * 8;

    if (tid < 64) {
        float rs = (n0 + tid < N) ? g_rowsum[n0 + tid] : 0.f;
        inv_sm[tid] = rs > 0.f ? 1.f / rs : 0.f;
    }

    unsigned long long acc[4][4];
    #pragma unroll
    for (int j = 0; j < 4; j++)
        #pragma unroll
        for (int p = 0; p < 4; p++) acc[j][p] = 0ull;

    #pragma unroll
    for (int kc = 0; kc < 5; kc++) {
        __syncthreads();
        #pragma unroll
        for (int it = 0; it < 8; it++) {
            int i = tid + it * 256;
            int k = i >> 5, qq = i & 31;
            float4 av = *(const float4*)(g_aT + (size_t)(kc * 64 + k) * 128 + qq * 4);
            *(float4*)&a_sm[k * 132 + qq * 4] = av;
        }
        #pragma unroll
        for (int it = 0; it < 16; it++) {
            int i = tid + it * 256;
            int n = i >> 6, k = i & 63;
            float val = 0.f;
            if (n0 + n < N) {
                if (kc < 2)       val = x[(size_t)(n0 + n) * 128 + kc * 64 + k];
                else if (kc < 4)  val = g_y[(size_t)(n0 + n) * 128 + (kc - 2) * 64 + k] * inv_sm[n];
                else              val = g_w[(size_t)(n0 + n) * 64 + k] * inv_sm[n];
            }
            z_sm[n * 65 + k] = make_float2(val, val);
        }
        __syncthreads();

        #pragma unroll 8
        for (int k = 0; k < 64; k++) {
            ulonglong2 A01 = *(const ulonglong2*)&a_sm[k * 132 + o0];
            ulonglong2 A23 = *(const ulonglong2*)&a_sm[k * 132 + o0 + 4];
            #pragma unroll
            for (int j = 0; j < 4; j++) {
                unsigned long long zd = *(const unsigned long long*)&z_sm[(nloc + j) * 65 + k];
                fma2(acc[j][0], zd, A01.x);
                fma2(acc[j][1], zd, A01.y);
                fma2(acc[j][2], zd, A23.x);
                fma2(acc[j][3], zd, A23.y);
            }
        }
    }

    #pragma unroll
    for (int j = 0; j < 4; j++) {
        int n = n0 + nloc + j;
        if (n < N) {
            bool ok = inv_sm[nloc + j] > 0.f;
            float o[8];
            #pragma unroll
            for (int p = 0; p < 4; p++) {
                float2 f = unpack2(acc[j][p]);
                o[2 * p] = f.x; o[2 * p + 1] = f.y;
            }
            #pragma unroll
            for (int q = 0; q < 8; q++)
                o[q] = ok ? (o[q] > 0.f ? o[q] : expm1f(o[q])) : 0.f;
            float* dp = out + (size_t)n * 128 + o0;
            *(float4*)dp = make_float4(o[0], o[1], o[2], o[3]);
            *(float4*)(dp + 4) = make_float4(o[4], o[5], o[6], o[7]);
        }
    }
}

// ---------------------------------------------------------------------------
extern "C" void kernel_launch(void* const* d_in, const int* in_sizes, int n_in,
                              void* d_out, int out_size) {
    const float* x     = (const float*)d_in[0];
    const int*   edge1 = (const int*)  d_in[1];
    const float* emb1  = (const float*)d_in[2];
    const int*   edge2 = (const int*)  d_in[3];
    const float* emb2  = (const float*)d_in[4];
    const float* a     = (const float*)d_in[5];
    const float* a2    = (const float*)d_in[6];
    float* out = (float*)d_out;

    int N  = in_sizes[0] / 128;
    int E1 = in_sizes[1] / 2;
    int E2 = in_sizes[3] / 2;

    vec_kernel<<<1, 320>>>(a, a2);
    transpose_a_kernel<<<160, 256>>>(a);
    sdot_kernel<<<(N + 3) / 4, 128>>>(x, N);
    zero_kernel<<<1024, 256>>>(N);
    hist_kernel<<<1024, 256>>>(edge1, edge2, E1, E2);
    scan_kernel<<<1, 1024>>>(N);
    passA_kernel<<<592, 256>>>(edge1, emb1, edge2, emb2, E1, E2);
    node_kernel<<<(N + 7) / 8, 256>>>(x, N);
    final_kernel<<<(N + 63) / 64, 256>>>(x, out, N);
}